// round 3
// baseline (speedup 1.0000x reference)
#include <cuda_runtime.h>
#include <cuda_bf16.h>
#include <cstdint>

#define NNODES 16384
#define HD 64
#define TLEN 12
#define NHEADS 8
#define KAUG 384          // augmented K: [hi*hi | lo*hi | hi*lo] x [input(64) | h(64)]

typedef __nv_bfloat16 bf16;

// ---------------- device scratch (allocation-free) ----------------
__device__ bf16  g_waug[2 * 8 * 256 * KAUG];              // permuted, split weights
__device__ float g_bias[2 * 8 * 256];                     // b_ih + b_hh (natural gate order)
__device__ bf16  g_xhi[TLEN * NNODES * HD];
__device__ bf16  g_xlo[TLEN * NNODES * HD];
// h state, parity double-buffered: [(l*2+parity)*8 + head][node][HD]
__device__ bf16  g_hhi[2 * 2 * 8 * NNODES * HD];
__device__ bf16  g_hlo[2 * 2 * 8 * NNODES * HD];
__device__ float g_c  [2 * 8 * NNODES * HD];
// final-layer hidden states fp32, channel c = head*TLEN + t
__device__ float g_hs [8 * TLEN * NNODES * HD];

__device__ __forceinline__ float sigf(float x) {
    return __fdividef(1.0f, 1.0f + __expf(-x));
}
__device__ __forceinline__ float tanh_fast(float x) {
    return 2.0f * sigf(2.0f * x) - 1.0f;
}
__device__ __forceinline__ uint32_t swz(uint32_t o) {       // SW128 xor swizzle
    return o ^ ((o >> 3) & 0x70);
}
__device__ __forceinline__ void ldsm4(uint32_t& r0, uint32_t& r1, uint32_t& r2, uint32_t& r3,
                                      uint32_t addr) {
    asm volatile("ldmatrix.sync.aligned.m8n8.x4.shared.b16 {%0,%1,%2,%3}, [%4];"
                 : "=r"(r0), "=r"(r1), "=r"(r2), "=r"(r3) : "r"(addr));
}
__device__ __forceinline__ void cpasync16(uint32_t saddr, const void* gaddr) {
    asm volatile("cp.async.cg.shared.global [%0], [%1], 16;" :: "r"(saddr), "l"(gaddr));
}

// ---------------- prep kernels (run every launch: deterministic) ----------------
__global__ void prep_w_kernel(const float* __restrict__ Wih, const float* __restrict__ Whh) {
    int idx = blockIdx.x * 256 + threadIdx.x;               // 2*8*256*384
    if (idx >= 2 * 8 * 256 * KAUG) return;
    int kp = idx % KAUG;
    int rp = (idx / KAUG) % 256;                            // permuted row
    int la = idx / (KAUG * 256);
    int c = kp / 64, j = kp % 64;
    // invert row permutation: rp = (u>>4)*64 + g*16 + (u&15)
    int ublk = rp >> 6, rem = rp & 63;
    int g = rem >> 4, u = (ublk << 4) | (rem & 15);
    const float* W = (c & 1) ? Whh : Wih;                   // even chunks: Wih, odd: Whh
    float v = W[((size_t)la * 256 + (g * 64 + u)) * 64 + j];
    bf16 hi = __float2bfloat16_rn(v);
    bf16 out = (c < 4) ? hi : __float2bfloat16_rn(v - __bfloat162float(hi));
    g_waug[((size_t)la * 256 + rp) * KAUG + kp] = out;
}

__global__ void prep_bias_kernel(const float* __restrict__ bih, const float* __restrict__ bhh) {
    int idx = blockIdx.x * 256 + threadIdx.x;
    if (idx < 2 * 8 * 256) g_bias[idx] = bih[idx] + bhh[idx];
}

__global__ void prep_x_kernel(const float* __restrict__ x) {
    int idx = blockIdx.x * 256 + threadIdx.x;
    if (idx >= TLEN * NNODES * HD) return;
    float v = x[idx];
    bf16 hi = __float2bfloat16_rn(v);
    g_xhi[idx] = hi;
    g_xlo[idx] = __float2bfloat16_rn(v - __bfloat162float(hi));
}

__global__ void prep_state_kernel(const float* __restrict__ h0, const float* __restrict__ c0) {
    size_t idx = (size_t)blockIdx.x * 256 + threadIdx.x;    // 2*8*N*64
    if (idx >= (size_t)2 * 8 * NNODES * HD) return;
    int u = idx & 63;
    size_t n = (idx >> 6) % NNODES;
    int a = (idx >> 6) / NNODES % 8;
    int l = (int)(idx / ((size_t)8 * NNODES * HD));
    size_t src = (((size_t)(a * 2 + l) * NNODES) + n) * HD + u;
    float hv = h0[src];
    bf16 hi = __float2bfloat16_rn(hv);
    size_t dst = ((size_t)((l * 2 + 1) * 8 + a) * NNODES + n) * HD + u;   // parity 1
    g_hhi[dst] = hi;
    g_hlo[dst] = __float2bfloat16_rn(hv - __bfloat162float(hi));
    g_c[((size_t)(l * 8 + a) * NNODES + n) * HD + u] = c0[src];
}

// ---------------- main LSTM step: tensor-core GEMM + fused cell ----------------
// grid (128 node-tiles, 8 heads, 2 (l,t) slots), 512 threads, 96KB dyn smem
__global__ void __launch_bounds__(512, 1)
lstm_step_mma(int s)
{
    const int l = blockIdx.z;
    const int t = (l == 0) ? s : s - 1;
    if (l == 0 && s >= TLEN) return;
    if (l == 1 && s == 0) return;

    extern __shared__ char smem[];
    // buffers: A[2] 16KB each, B[2] 32KB each
    uint32_t sbase = (uint32_t)__cvta_generic_to_shared(smem);
    const uint32_t Ab[2] = { sbase, sbase + 16384 };
    const uint32_t Bb[2] = { sbase + 32768, sbase + 65536 };

    const int tid = threadIdx.x;
    const int lane = tid & 31, w = tid >> 5;
    const int wm = w & 3, wn = w >> 2;
    const int a = blockIdx.y;
    const size_t tile = (size_t)blockIdx.x * 128;

    // A-operand sources for the 6 augmented k-chunks
    const bf16 *inhi, *inlo;
    if (l == 0) {
        inhi = g_xhi + (size_t)t * NNODES * HD;
        inlo = g_xlo + (size_t)t * NNODES * HD;
    } else {
        size_t o = (size_t)(((t & 1)) * 8 + a) * NNODES * HD;   // layer0, parity t&1
        inhi = g_hhi + o; inlo = g_hlo + o;
    }
    const int pin = (t + 1) & 1;
    size_t hpo = (size_t)((l * 2 + pin) * 8 + a) * NNODES * HD;
    const bf16* hphi = g_hhi + hpo;
    const bf16* hplo = g_hlo + hpo;
    const bf16* Aptr[6] = { inhi, hphi, inlo, hplo, inhi, hphi };
    const bf16* wptr = g_waug + (size_t)(l * 8 + a) * 256 * KAUG;

    float acc[2][8][4];
    #pragma unroll
    for (int mi = 0; mi < 2; mi++)
        #pragma unroll
        for (int n8 = 0; n8 < 8; n8++)
            #pragma unroll
            for (int e = 0; e < 4; e++) acc[mi][n8][e] = 0.0f;

    // chunk loaders
    auto loadA = [&](int c, int buf) {
        #pragma unroll
        for (int it = 0; it < 2; it++) {
            int idx = tid + it * 512;                 // 1024 x 16B
            int r = idx >> 3, j = idx & 7;
            cpasync16(Ab[buf] + swz(r * 128 + j * 16),
                      Aptr[c] + (tile + r) * HD + j * 8);
        }
    };
    auto loadB = [&](int c, int buf) {
        #pragma unroll
        for (int it = 0; it < 4; it++) {
            int idx = tid + it * 512;                 // 2048 x 16B
            int r = idx >> 3, j = idx & 7;
            cpasync16(Bb[buf] + swz(r * 128 + j * 16),
                      wptr + (size_t)r * KAUG + c * 64 + j * 8);
        }
    };

    loadA(0, 0); loadB(0, 0);
    asm volatile("cp.async.commit_group;");
    loadA(1, 1); loadB(1, 1);
    asm volatile("cp.async.commit_group;");

    #pragma unroll 1
    for (int c = 0; c < 6; c++) {
        if (c < 5) asm volatile("cp.async.wait_group 1;");
        else       asm volatile("cp.async.wait_group 0;");
        __syncthreads();
        const int buf = c & 1;
        #pragma unroll
        for (int ks = 0; ks < 4; ks++) {
            const int kb = ks * 32;                    // k0*2 bytes
            uint32_t av[2][4];
            #pragma unroll
            for (int mi = 0; mi < 2; mi++) {
                int r0 = wm * 32 + mi * 16;
                uint32_t off = (uint32_t)((r0 + (lane & 15)) * 128 + kb + ((lane >> 4) << 4));
                ldsm4(av[mi][0], av[mi][1], av[mi][2], av[mi][3], Ab[buf] + swz(off));
            }
            #pragma unroll
            for (int i = 0; i < 4; i++) {
                int n0 = wn * 64 + i * 16;
                uint32_t off = (uint32_t)((n0 + (lane & 15)) * 128 + kb + ((lane >> 4) << 4));
                uint32_t b0, b1, b2, b3;
                ldsm4(b0, b1, b2, b3, Bb[buf] + swz(off));
                #pragma unroll
                for (int mi = 0; mi < 2; mi++) {
                    asm volatile(
                        "mma.sync.aligned.m16n8k16.row.col.f32.bf16.bf16.f32 "
                        "{%0,%1,%2,%3},{%4,%5,%6,%7},{%8,%9},{%0,%1,%2,%3};"
                        : "+f"(acc[mi][i*2][0]), "+f"(acc[mi][i*2][1]),
                          "+f"(acc[mi][i*2][2]), "+f"(acc[mi][i*2][3])
                        : "r"(av[mi][0]), "r"(av[mi][1]), "r"(av[mi][2]), "r"(av[mi][3]),
                          "r"(b0), "r"(b2));
                    asm volatile(
                        "mma.sync.aligned.m16n8k16.row.col.f32.bf16.bf16.f32 "
                        "{%0,%1,%2,%3},{%4,%5,%6,%7},{%8,%9},{%0,%1,%2,%3};"
                        : "+f"(acc[mi][i*2+1][0]), "+f"(acc[mi][i*2+1][1]),
                          "+f"(acc[mi][i*2+1][2]), "+f"(acc[mi][i*2+1][3])
                        : "r"(av[mi][0]), "r"(av[mi][1]), "r"(av[mi][2]), "r"(av[mi][3]),
                          "r"(b1), "r"(b3));
                }
            }
        }
        __syncthreads();
        if (c + 2 <= 5) {
            loadA(c + 2, buf); loadB(c + 2, buf);
            asm volatile("cp.async.commit_group;");
        }
    }

    // ---------------- fused LSTM cell epilogue (thread-local: row perm gives all 4 gates) ----
    const float* biasp = g_bias + (l * 8 + a) * 256;
    float* cbase = g_c + (size_t)(l * 8 + a) * NNODES * HD;
    size_t ho = (size_t)((l * 2 + (t & 1)) * 8 + a) * NNODES * HD;
    bf16* hhi_o = g_hhi + ho;
    bf16* hlo_o = g_hlo + ho;
    float* hs_o = g_hs + (size_t)(a * TLEN + t) * NNODES * HD;

    #pragma unroll
    for (int mi = 0; mi < 2; mi++)
        #pragma unroll
        for (int rs = 0; rs < 2; rs++) {
            size_t n = tile + wm * 32 + mi * 16 + (lane >> 2) + rs * 8;
            #pragma unroll
            for (int vh = 0; vh < 2; vh++)
                #pragma unroll
                for (int vv = 0; vv < 2; vv++) {
                    int u = wn * 16 + vh * 8 + ((lane & 3) << 1) + vv;
                    int e = rs * 2 + vv;
                    float zi = acc[mi][0 + vh][e] + biasp[u];
                    float zf = acc[mi][2 + vh][e] + biasp[64 + u];
                    float zg = acc[mi][4 + vh][e] + biasp[128 + u];
                    float zo = acc[mi][6 + vh][e] + biasp[192 + u];
                    size_t off = n * HD + u;
                    float cp = cbase[off];
                    float cn = sigf(zf) * cp + sigf(zi) * tanh_fast(zg);
                    float hn = sigf(zo) * tanh_fast(cn);
                    cbase[off] = cn;
                    bf16 hi = __float2bfloat16_rn(hn);
                    hhi_o[off] = hi;
                    hlo_o[off] = __float2bfloat16_rn(hn - __bfloat162float(hi));
                    if (l == 1) hs_o[off] = hn;
                }
        }
}

// ---------------- 1x1 conv over channels (heads*T -> T) ----------------
__global__ void conv_kernel(const float* __restrict__ conv_w,
                            const float* __restrict__ conv_b,
                            float* __restrict__ out)
{
    __shared__ float ws[TLEN * 96];
    const int tid = threadIdx.x;
    for (int i = tid; i < TLEN * 96; i += 256) ws[i] = conv_w[i];
    __syncthreads();

    const size_t P = (size_t)NNODES * HD;
    const size_t base = ((size_t)blockIdx.x * 256 + tid) * 4;

    float4 accv[TLEN];
    #pragma unroll
    for (int o = 0; o < TLEN; o++) {
        float b = conv_b[o];
        accv[o] = make_float4(b, b, b, b);
    }
    #pragma unroll 4
    for (int c = 0; c < 96; c++) {
        float4 v = *(const float4*)&g_hs[(size_t)c * P + base];
        #pragma unroll
        for (int o = 0; o < TLEN; o++) {
            float wv = ws[o * 96 + c];
            accv[o].x += wv * v.x; accv[o].y += wv * v.y;
            accv[o].z += wv * v.z; accv[o].w += wv * v.w;
        }
    }
    #pragma unroll
    for (int o = 0; o < TLEN; o++)
        *(float4*)&out[(size_t)o * P + base] = accv[o];
}

extern "C" void kernel_launch(void* const* d_in, const int* in_sizes, int n_in,
                              void* d_out, int out_size)
{
    const float* x   = (const float*)d_in[0];
    const float* Wih = (const float*)d_in[1];
    const float* Whh = (const float*)d_in[2];
    const float* bih = (const float*)d_in[3];
    const float* bhh = (const float*)d_in[4];
    const float* h0  = (const float*)d_in[5];
    const float* c0  = (const float*)d_in[6];
    const float* cw  = (const float*)d_in[7];
    const float* cb  = (const float*)d_in[8];
    float* out = (float*)d_out;

    static bool attr_set = false;
    if (!attr_set) {
        cudaFuncSetAttribute(lstm_step_mma,
                             cudaFuncAttributeMaxDynamicSharedMemorySize, 98304);
        attr_set = true;
    }

    prep_w_kernel<<<(2 * 8 * 256 * KAUG + 255) / 256, 256>>>(Wih, Whh);
    prep_bias_kernel<<<(2 * 8 * 256 + 255) / 256, 256>>>(bih, bhh);
    prep_x_kernel<<<(TLEN * NNODES * HD + 255) / 256, 256>>>(x);
    prep_state_kernel<<<(2 * 8 * NNODES * HD + 255) / 256, 256>>>(h0, c0);

    dim3 grid(NNODES / 128, NHEADS, 2);
    for (int s = 0; s < TLEN + 1; s++)
        lstm_step_mma<<<grid, 512, 98304>>>(s);

    conv_kernel<<<(NNODES * HD) / 1024, 256>>>(cw, cb, out);
}

// round 4
// speedup vs baseline: 1.0012x; 1.0012x over previous
#include <cuda_runtime.h>
#include <cuda_bf16.h>
#include <cstdint>

#define NNODES 16384
#define HD 64
#define TLEN 12
#define NHEADS 8
#define KAUG 384          // augmented K: [hi*hi | lo*hi | hi*lo] x [input(64) | h(64)]

typedef __nv_bfloat16 bf16;

// ---------------- device scratch (allocation-free) ----------------
__device__ bf16  g_waug[2 * 8 * 256 * KAUG];              // permuted, split weights
__device__ float g_bias[2 * 8 * 256];                     // b_ih + b_hh (natural gate order)
__device__ bf16  g_xhi[TLEN * NNODES * HD];
__device__ bf16  g_xlo[TLEN * NNODES * HD];
// h state, parity double-buffered: [(l*2+parity)*8 + head][node][HD]
__device__ bf16  g_hhi[2 * 2 * 8 * NNODES * HD];
__device__ bf16  g_hlo[2 * 2 * 8 * NNODES * HD];
__device__ float g_c  [2 * 8 * NNODES * HD];
// final-layer hidden states fp32, channel c = head*TLEN + t
__device__ float g_hs [8 * TLEN * NNODES * HD];

__device__ __forceinline__ float sigf(float x) {
    return __fdividef(1.0f, 1.0f + __expf(-x));
}
__device__ __forceinline__ float tanh_fast(float x) {
    return 2.0f * sigf(2.0f * x) - 1.0f;
}
__device__ __forceinline__ uint32_t swz(uint32_t o) {       // SW128 xor swizzle
    return o ^ ((o >> 3) & 0x70);
}
__device__ __forceinline__ void ldsm4(uint32_t& r0, uint32_t& r1, uint32_t& r2, uint32_t& r3,
                                      uint32_t addr) {
    asm volatile("ldmatrix.sync.aligned.m8n8.x4.shared.b16 {%0,%1,%2,%3}, [%4];"
                 : "=r"(r0), "=r"(r1), "=r"(r2), "=r"(r3) : "r"(addr));
}
__device__ __forceinline__ void cpasync16(uint32_t saddr, const void* gaddr) {
    asm volatile("cp.async.cg.shared.global [%0], [%1], 16;" :: "r"(saddr), "l"(gaddr));
}

// ---------------- prep kernels (run every launch: deterministic) ----------------
__global__ void prep_w_kernel(const float* __restrict__ Wih, const float* __restrict__ Whh) {
    int idx = blockIdx.x * 256 + threadIdx.x;               // 2*8*256*384
    if (idx >= 2 * 8 * 256 * KAUG) return;
    int kp = idx % KAUG;
    int rp = (idx / KAUG) % 256;                            // permuted row
    int la = idx / (KAUG * 256);
    int c = kp / 64, j = kp % 64;
    // invert row permutation: rp = (u>>4)*64 + g*16 + (u&15)
    int ublk = rp >> 6, rem = rp & 63;
    int g = rem >> 4, u = (ublk << 4) | (rem & 15);
    const float* W = (c & 1) ? Whh : Wih;                   // even chunks: Wih, odd: Whh
    float v = W[((size_t)la * 256 + (g * 64 + u)) * 64 + j];
    bf16 hi = __float2bfloat16_rn(v);
    bf16 out = (c < 4) ? hi : __float2bfloat16_rn(v - __bfloat162float(hi));
    g_waug[((size_t)la * 256 + rp) * KAUG + kp] = out;
}

__global__ void prep_bias_kernel(const float* __restrict__ bih, const float* __restrict__ bhh) {
    int idx = blockIdx.x * 256 + threadIdx.x;
    if (idx < 2 * 8 * 256) g_bias[idx] = bih[idx] + bhh[idx];
}

__global__ void prep_x_kernel(const float* __restrict__ x) {
    int idx = blockIdx.x * 256 + threadIdx.x;
    if (idx >= TLEN * NNODES * HD) return;
    float v = x[idx];
    bf16 hi = __float2bfloat16_rn(v);
    g_xhi[idx] = hi;
    g_xlo[idx] = __float2bfloat16_rn(v - __bfloat162float(hi));
}

__global__ void prep_state_kernel(const float* __restrict__ h0, const float* __restrict__ c0) {
    size_t idx = (size_t)blockIdx.x * 256 + threadIdx.x;    // 2*8*N*64
    if (idx >= (size_t)2 * 8 * NNODES * HD) return;
    int u = idx & 63;
    size_t n = (idx >> 6) % NNODES;
    int a = (idx >> 6) / NNODES % 8;
    int l = (int)(idx / ((size_t)8 * NNODES * HD));
    size_t src = (((size_t)(a * 2 + l) * NNODES) + n) * HD + u;
    float hv = h0[src];
    bf16 hi = __float2bfloat16_rn(hv);
    size_t dst = ((size_t)((l * 2 + 1) * 8 + a) * NNODES + n) * HD + u;   // parity 1
    g_hhi[dst] = hi;
    g_hlo[dst] = __float2bfloat16_rn(hv - __bfloat162float(hi));
    g_c[((size_t)(l * 8 + a) * NNODES + n) * HD + u] = c0[src];
}

// ---------------- main LSTM step: tensor-core GEMM + fused cell ----------------
// grid (128 node-tiles, 8 heads, 2 (l,t) slots), 512 threads, 96KB dyn smem
__global__ void __launch_bounds__(512, 1)
lstm_step_mma(int s)
{
    const int l = blockIdx.z;
    const int t = (l == 0) ? s : s - 1;
    if (l == 0 && s >= TLEN) return;
    if (l == 1 && s == 0) return;

    extern __shared__ char smem[];
    // buffers: A[2] 16KB each, B[2] 32KB each
    uint32_t sbase = (uint32_t)__cvta_generic_to_shared(smem);
    const uint32_t Ab[2] = { sbase, sbase + 16384 };
    const uint32_t Bb[2] = { sbase + 32768, sbase + 65536 };

    const int tid = threadIdx.x;
    const int lane = tid & 31, w = tid >> 5;
    const int wm = w & 3, wn = w >> 2;
    const int a = blockIdx.y;
    const size_t tile = (size_t)blockIdx.x * 128;

    // A-operand sources for the 6 augmented k-chunks
    const bf16 *inhi, *inlo;
    if (l == 0) {
        inhi = g_xhi + (size_t)t * NNODES * HD;
        inlo = g_xlo + (size_t)t * NNODES * HD;
    } else {
        size_t o = (size_t)(((t & 1)) * 8 + a) * NNODES * HD;   // layer0, parity t&1
        inhi = g_hhi + o; inlo = g_hlo + o;
    }
    const int pin = (t + 1) & 1;
    size_t hpo = (size_t)((l * 2 + pin) * 8 + a) * NNODES * HD;
    const bf16* hphi = g_hhi + hpo;
    const bf16* hplo = g_hlo + hpo;
    const bf16* Aptr[6] = { inhi, hphi, inlo, hplo, inhi, hphi };
    const bf16* wptr = g_waug + (size_t)(l * 8 + a) * 256 * KAUG;

    float acc[2][8][4];
    #pragma unroll
    for (int mi = 0; mi < 2; mi++)
        #pragma unroll
        for (int n8 = 0; n8 < 8; n8++)
            #pragma unroll
            for (int e = 0; e < 4; e++) acc[mi][n8][e] = 0.0f;

    // chunk loaders
    auto loadA = [&](int c, int buf) {
        #pragma unroll
        for (int it = 0; it < 2; it++) {
            int idx = tid + it * 512;                 // 1024 x 16B
            int r = idx >> 3, j = idx & 7;
            cpasync16(Ab[buf] + swz(r * 128 + j * 16),
                      Aptr[c] + (tile + r) * HD + j * 8);
        }
    };
    auto loadB = [&](int c, int buf) {
        #pragma unroll
        for (int it = 0; it < 4; it++) {
            int idx = tid + it * 512;                 // 2048 x 16B
            int r = idx >> 3, j = idx & 7;
            cpasync16(Bb[buf] + swz(r * 128 + j * 16),
                      wptr + (size_t)r * KAUG + c * 64 + j * 8);
        }
    };

    loadA(0, 0); loadB(0, 0);
    asm volatile("cp.async.commit_group;");
    loadA(1, 1); loadB(1, 1);
    asm volatile("cp.async.commit_group;");

    #pragma unroll 1
    for (int c = 0; c < 6; c++) {
        if (c < 5) asm volatile("cp.async.wait_group 1;");
        else       asm volatile("cp.async.wait_group 0;");
        __syncthreads();
        const int buf = c & 1;
        #pragma unroll
        for (int ks = 0; ks < 4; ks++) {
            const int kb = ks * 32;                    // k0*2 bytes
            uint32_t av[2][4];
            #pragma unroll
            for (int mi = 0; mi < 2; mi++) {
                int r0 = wm * 32 + mi * 16;
                uint32_t off = (uint32_t)((r0 + (lane & 15)) * 128 + kb + ((lane >> 4) << 4));
                ldsm4(av[mi][0], av[mi][1], av[mi][2], av[mi][3], Ab[buf] + swz(off));
            }
            #pragma unroll
            for (int i = 0; i < 4; i++) {
                int n0 = wn * 64 + i * 16;
                uint32_t off = (uint32_t)((n0 + (lane & 15)) * 128 + kb + ((lane >> 4) << 4));
                uint32_t b0, b1, b2, b3;
                ldsm4(b0, b1, b2, b3, Bb[buf] + swz(off));
                #pragma unroll
                for (int mi = 0; mi < 2; mi++) {
                    asm volatile(
                        "mma.sync.aligned.m16n8k16.row.col.f32.bf16.bf16.f32 "
                        "{%0,%1,%2,%3},{%4,%5,%6,%7},{%8,%9},{%0,%1,%2,%3};"
                        : "+f"(acc[mi][i*2][0]), "+f"(acc[mi][i*2][1]),
                          "+f"(acc[mi][i*2][2]), "+f"(acc[mi][i*2][3])
                        : "r"(av[mi][0]), "r"(av[mi][1]), "r"(av[mi][2]), "r"(av[mi][3]),
                          "r"(b0), "r"(b2));
                    asm volatile(
                        "mma.sync.aligned.m16n8k16.row.col.f32.bf16.bf16.f32 "
                        "{%0,%1,%2,%3},{%4,%5,%6,%7},{%8,%9},{%0,%1,%2,%3};"
                        : "+f"(acc[mi][i*2+1][0]), "+f"(acc[mi][i*2+1][1]),
                          "+f"(acc[mi][i*2+1][2]), "+f"(acc[mi][i*2+1][3])
                        : "r"(av[mi][0]), "r"(av[mi][1]), "r"(av[mi][2]), "r"(av[mi][3]),
                          "r"(b1), "r"(b3));
                }
            }
        }
        __syncthreads();
        if (c + 2 <= 5) {
            loadA(c + 2, buf); loadB(c + 2, buf);
            asm volatile("cp.async.commit_group;");
        }
    }

    // ---------------- fused LSTM cell epilogue (thread-local: row perm gives all 4 gates) ----
    const float* biasp = g_bias + (l * 8 + a) * 256;
    float* cbase = g_c + (size_t)(l * 8 + a) * NNODES * HD;
    size_t ho = (size_t)((l * 2 + (t & 1)) * 8 + a) * NNODES * HD;
    bf16* hhi_o = g_hhi + ho;
    bf16* hlo_o = g_hlo + ho;
    float* hs_o = g_hs + (size_t)(a * TLEN + t) * NNODES * HD;

    #pragma unroll
    for (int mi = 0; mi < 2; mi++)
        #pragma unroll
        for (int rs = 0; rs < 2; rs++) {
            size_t n = tile + wm * 32 + mi * 16 + (lane >> 2) + rs * 8;
            #pragma unroll
            for (int vh = 0; vh < 2; vh++)
                #pragma unroll
                for (int vv = 0; vv < 2; vv++) {
                    int u = wn * 16 + vh * 8 + ((lane & 3) << 1) + vv;
                    int e = rs * 2 + vv;
                    float zi = acc[mi][0 + vh][e] + biasp[u];
                    float zf = acc[mi][2 + vh][e] + biasp[64 + u];
                    float zg = acc[mi][4 + vh][e] + biasp[128 + u];
                    float zo = acc[mi][6 + vh][e] + biasp[192 + u];
                    size_t off = n * HD + u;
                    float cp = cbase[off];
                    float cn = sigf(zf) * cp + sigf(zi) * tanh_fast(zg);
                    float hn = sigf(zo) * tanh_fast(cn);
                    cbase[off] = cn;
                    bf16 hi = __float2bfloat16_rn(hn);
                    hhi_o[off] = hi;
                    hlo_o[off] = __float2bfloat16_rn(hn - __bfloat162float(hi));
                    if (l == 1) hs_o[off] = hn;
                }
        }
}

// ---------------- 1x1 conv over channels (heads*T -> T) ----------------
__global__ void conv_kernel(const float* __restrict__ conv_w,
                            const float* __restrict__ conv_b,
                            float* __restrict__ out)
{
    __shared__ float ws[TLEN * 96];
    const int tid = threadIdx.x;
    for (int i = tid; i < TLEN * 96; i += 256) ws[i] = conv_w[i];
    __syncthreads();

    const size_t P = (size_t)NNODES * HD;
    const size_t base = ((size_t)blockIdx.x * 256 + tid) * 4;

    float4 accv[TLEN];
    #pragma unroll
    for (int o = 0; o < TLEN; o++) {
        float b = conv_b[o];
        accv[o] = make_float4(b, b, b, b);
    }
    #pragma unroll 4
    for (int c = 0; c < 96; c++) {
        float4 v = *(const float4*)&g_hs[(size_t)c * P + base];
        #pragma unroll
        for (int o = 0; o < TLEN; o++) {
            float wv = ws[o * 96 + c];
            accv[o].x += wv * v.x; accv[o].y += wv * v.y;
            accv[o].z += wv * v.z; accv[o].w += wv * v.w;
        }
    }
    #pragma unroll
    for (int o = 0; o < TLEN; o++)
        *(float4*)&out[(size_t)o * P + base] = accv[o];
}

extern "C" void kernel_launch(void* const* d_in, const int* in_sizes, int n_in,
                              void* d_out, int out_size)
{
    const float* x   = (const float*)d_in[0];
    const float* Wih = (const float*)d_in[1];
    const float* Whh = (const float*)d_in[2];
    const float* bih = (const float*)d_in[3];
    const float* bhh = (const float*)d_in[4];
    const float* h0  = (const float*)d_in[5];
    const float* c0  = (const float*)d_in[6];
    const float* cw  = (const float*)d_in[7];
    const float* cb  = (const float*)d_in[8];
    float* out = (float*)d_out;

    static bool attr_set = false;
    if (!attr_set) {
        cudaFuncSetAttribute(lstm_step_mma,
                             cudaFuncAttributeMaxDynamicSharedMemorySize, 98304);
        attr_set = true;
    }

    prep_w_kernel<<<(2 * 8 * 256 * KAUG + 255) / 256, 256>>>(Wih, Whh);
    prep_bias_kernel<<<(2 * 8 * 256 + 255) / 256, 256>>>(bih, bhh);
    prep_x_kernel<<<(TLEN * NNODES * HD + 255) / 256, 256>>>(x);
    prep_state_kernel<<<(2 * 8 * NNODES * HD + 255) / 256, 256>>>(h0, c0);

    dim3 grid(NNODES / 128, NHEADS, 2);
    for (int s = 0; s < TLEN + 1; s++)
        lstm_step_mma<<<grid, 512, 98304>>>(s);

    conv_kernel<<<(NNODES * HD) / 1024, 256>>>(cw, cb, out);
}

// round 7
// speedup vs baseline: 3.8458x; 3.8413x over previous
#include <cuda_runtime.h>
#include <cuda_fp16.h>
#include <cstdint>

#define NNODES 16384
#define HD 64
#define TLEN 12
#define NHEADS 8

typedef uint32_t u32;

// ---------------- device globals (allocation-free scratch) ----------------
__device__ __half g_wh[2 * 2 * 8 * 256 * 64];   // [(l*2+s)*8+a][row-perm 256][64] fp16
__device__ float  g_bias[2 * 8 * 256];          // b_ih+b_hh, natural gate order
__device__ __half g_xh[TLEN * NNODES * HD];     // x fp16
__device__ __half g_h0h[2 * 8 * NNODES * HD];   // initial h fp16, [(l*8+a)][n][u]
__device__ float  g_hs[8 * TLEN * NNODES * HD]; // layer-1 h fp32, ch = a*12+t

// ---------------- helpers ----------------
__device__ __forceinline__ u32 swz(u32 o) { return o ^ ((o >> 3) & 0x70); }
__device__ __forceinline__ float ex2f(float x) {
    float r; asm("ex2.approx.f32 %0, %1;" : "=f"(r) : "f"(x)); return r;
}
__device__ __forceinline__ float rcpf(float x) {
    float r; asm("rcp.approx.f32 %0, %1;" : "=f"(r) : "f"(x)); return r;
}
__device__ __forceinline__ float sigf(float x) {
    return rcpf(1.0f + ex2f(-1.4426950408889634f * x));
}
__device__ __forceinline__ float tanhv(float x) {
    return __fmaf_rn(2.0f, rcpf(1.0f + ex2f(-2.8853900817779268f * x)), -1.0f);
}
__device__ __forceinline__ void cpasync16(u32 saddr, const void* gaddr) {
    asm volatile("cp.async.cg.shared.global [%0], [%1], 16;" :: "r"(saddr), "l"(gaddr));
}
#define CP_COMMIT() asm volatile("cp.async.commit_group;" ::: "memory")
#define CP_WAIT0()  asm volatile("cp.async.wait_group 0;" ::: "memory")

__device__ __forceinline__ void ldsm4(u32& r0, u32& r1, u32& r2, u32& r3, u32 addr) {
    asm volatile("ldmatrix.sync.aligned.m8n8.x4.shared.b16 {%0,%1,%2,%3}, [%4];"
                 : "=r"(r0), "=r"(r1), "=r"(r2), "=r"(r3) : "r"(addr));
}

// ---------------- prep kernels ----------------
__global__ void prep_w_kernel(const float* __restrict__ Wih, const float* __restrict__ Whh) {
    int idx = blockIdx.x * 256 + threadIdx.x;        // 2*2*8*256*64 = 524288
    if (idx >= 2 * 2 * 8 * 256 * 64) return;
    int j  = idx & 63;
    int rp = (idx >> 6) & 255;
    int a  = (idx >> 14) & 7;
    int s  = (idx >> 17) & 1;
    int l  = idx >> 18;
    int u = ((rp >> 6) << 4) | (rp & 15);
    int g = (rp >> 4) & 3;
    const float* W = s ? Whh : Wih;
    float v = W[(((size_t)(l * 8 + a)) * 256 + (g * 64 + u)) * 64 + j];
    g_wh[((size_t)((l * 2 + s) * 8 + a)) * 16384 + rp * 64 + j] = __float2half_rn(v);
}

__global__ void prep_bias_kernel(const float* __restrict__ bih, const float* __restrict__ bhh) {
    int idx = blockIdx.x * 256 + threadIdx.x;
    if (idx < 2 * 8 * 256) g_bias[idx] = bih[idx] + bhh[idx];
}

__global__ void prep_x_kernel(const float* __restrict__ x) {
    int idx = blockIdx.x * 256 + threadIdx.x;
    if (idx < TLEN * NNODES * HD) g_xh[idx] = __float2half_rn(x[idx]);
}

__global__ void prep_h0_kernel(const float* __restrict__ h0) {
    size_t idx = (size_t)blockIdx.x * 256 + threadIdx.x;   // 2*8*NN*64
    if (idx >= (size_t)2 * 8 * NNODES * HD) return;
    int u = idx & 63;
    size_t n = (idx >> 6) % NNODES;
    int a = (int)((idx >> 6) / NNODES) % 8;
    int l = (int)(idx / ((size_t)8 * NNODES * HD));
    g_h0h[idx] = __float2half_rn(h0[(((size_t)(a * 2 + l)) * NNODES + n) * HD + u]);
}

// ---------------- fused LSTM: 2 layers x 12 steps per CTA ----------------
#define S_W    0u          // 4 x 32KB weight chunks: (l*2+c)
#define S_AX   131072u     // 2 x 16KB x buffers
#define S_AH0  163840u     // 16KB
#define S_AH1  180224u     // 16KB
#define S_BIAS 196608u     // 512 floats
#define SMEM_TOTAL 198656

__device__ __forceinline__ void stage_tile(u32 dst, const __half* src, int tid) {
    #pragma unroll
    for (int i = 0; i < 2; i++) {
        int idx = tid + i * 512;                  // 0..1023
        int r = idx >> 3, j = idx & 7;
        cpasync16(dst + swz((u32)(r * 128 + j * 16)), src + r * 64 + j * 8);
    }
}

__global__ void __launch_bounds__(512, 1)
lstm_fused(const float* __restrict__ c0)
{
    extern __shared__ __align__(1024) char smem[];
    const u32 sb = (u32)__cvta_generic_to_shared(smem);

    const int tid  = threadIdx.x;
    const int lane = tid & 31, w = tid >> 5;
    const int wm = w & 3, wn = w >> 2;
    const int a = blockIdx.y;
    const int tile = blockIdx.x * 128;

    // ---- stage weights (4 x 32KB) + x0 + h0 tiles ----
    #pragma unroll
    for (int i = 0; i < 16; i++) {
        int idx = tid + i * 512;                  // 0..8191
        int ci = idx >> 11, rem = idx & 2047;
        int r = rem >> 3, j = rem & 7;
        cpasync16(sb + S_W + ci * 32768 + swz((u32)(r * 128 + j * 16)),
                  g_wh + ((size_t)(ci * 8 + a)) * 16384 + r * 64 + j * 8);
    }
    stage_tile(sb + S_AX, g_xh + (size_t)tile * 64, tid);
    stage_tile(sb + S_AH0, g_h0h + ((size_t)(0 * 8 + a) * NNODES + tile) * 64, tid);
    stage_tile(sb + S_AH1, g_h0h + ((size_t)(1 * 8 + a) * NNODES + tile) * 64, tid);
    CP_COMMIT();

    // bias -> smem
    {
        float* sB = (float*)(smem + S_BIAS);
        int l = tid >> 8, r = tid & 255;
        sB[tid] = g_bias[(l * 8 + a) * 256 + r];
    }

    // c state in registers: cst[l*8 + mi*4 + rs*2 + vh] = (c(vv=0), c(vv=1))
    float2 cst[16];
    #pragma unroll
    for (int l = 0; l < 2; l++)
        #pragma unroll
        for (int mi = 0; mi < 2; mi++)
            #pragma unroll
            for (int rs = 0; rs < 2; rs++)
                #pragma unroll
                for (int vh = 0; vh < 2; vh++) {
                    int nn = wm * 32 + mi * 16 + (lane >> 2) + rs * 8;
                    int u0 = wn * 16 + vh * 8 + (lane & 3) * 2;
                    cst[l * 8 + mi * 4 + rs * 2 + vh] =
                        *(const float2*)&c0[(((size_t)(a * 2 + l)) * NNODES + tile + nn) * 64 + u0];
                }

    CP_WAIT0();
    __syncthreads();

    float acc[2][8][4];

    for (int t = 0; t < TLEN; t++) {
        if (t + 1 < TLEN)
            stage_tile(sb + S_AX + ((t + 1) & 1) * 16384,
                       g_xh + ((size_t)(t + 1) * NNODES + tile) * 64, tid);
        CP_COMMIT();

        #pragma unroll
        for (int l = 0; l < 2; l++) {
            const u32 Ab0 = l ? (sb + S_AH0) : (sb + S_AX + (t & 1) * 16384);
            const u32 Ab1 = l ? (sb + S_AH1) : (sb + S_AH0);

            #pragma unroll
            for (int mi = 0; mi < 2; mi++)
                #pragma unroll
                for (int n8 = 0; n8 < 8; n8++)
                    #pragma unroll
                    for (int e = 0; e < 4; e++) acc[mi][n8][e] = 0.0f;

            // ---- mainloop: 2 K-chunks of 64 ----
            #pragma unroll
            for (int c = 0; c < 2; c++) {
                const u32 Ab = c ? Ab1 : Ab0;
                const u32 Wb = sb + S_W + (l * 2 + c) * 32768;
                #pragma unroll
                for (int ks = 0; ks < 4; ks++) {
                    const int kb = ks * 32;
                    u32 av[2][4];
                    #pragma unroll
                    for (int mi = 0; mi < 2; mi++) {
                        u32 off = (u32)((wm * 32 + mi * 16 + (lane & 15)) * 128 + kb + ((lane >> 4) << 4));
                        ldsm4(av[mi][0], av[mi][1], av[mi][2], av[mi][3], Ab + swz(off));
                    }
                    #pragma unroll
                    for (int i = 0; i < 4; i++) {
                        u32 off = (u32)((wn * 64 + i * 16 + (lane & 15)) * 128 + kb + ((lane >> 4) << 4));
                        u32 b0, b1, b2, b3;
                        ldsm4(b0, b1, b2, b3, Wb + swz(off));
                        #pragma unroll
                        for (int mi = 0; mi < 2; mi++) {
                            asm volatile(
                                "mma.sync.aligned.m16n8k16.row.col.f32.f16.f16.f32 "
                                "{%0,%1,%2,%3},{%4,%5,%6,%7},{%8,%9},{%0,%1,%2,%3};"
                                : "+f"(acc[mi][i*2][0]), "+f"(acc[mi][i*2][1]),
                                  "+f"(acc[mi][i*2][2]), "+f"(acc[mi][i*2][3])
                                : "r"(av[mi][0]), "r"(av[mi][1]), "r"(av[mi][2]), "r"(av[mi][3]),
                                  "r"(b0), "r"(b2));
                            asm volatile(
                                "mma.sync.aligned.m16n8k16.row.col.f32.f16.f16.f32 "
                                "{%0,%1,%2,%3},{%4,%5,%6,%7},{%8,%9},{%0,%1,%2,%3};"
                                : "+f"(acc[mi][i*2+1][0]), "+f"(acc[mi][i*2+1][1]),
                                  "+f"(acc[mi][i*2+1][2]), "+f"(acc[mi][i*2+1][3])
                                : "r"(av[mi][0]), "r"(av[mi][1]), "r"(av[mi][2]), "r"(av[mi][3]),
                                  "r"(b1), "r"(b3));
                        }
                    }
                }
            }
            __syncthreads();

            // ---- epilogue: gate order i,f,g,o mapped by row permutation ----
            {
                const float* sB = (const float*)(smem + S_BIAS) + l * 256;
                char* hdst = smem + (l ? S_AH1 : S_AH0);
                float* hs_o = g_hs + ((size_t)(a * TLEN + t) * NNODES + tile) * 64;
                #pragma unroll
                for (int mi = 0; mi < 2; mi++)
                    #pragma unroll
                    for (int rs = 0; rs < 2; rs++) {
                        const int nn = wm * 32 + mi * 16 + (lane >> 2) + rs * 8;
                        const int e = rs * 2;
                        #pragma unroll
                        for (int vh = 0; vh < 2; vh++) {
                            const int u0 = wn * 16 + vh * 8 + (lane & 3) * 2;
                            const int ci = l * 8 + mi * 4 + rs * 2 + vh;
                            float2 cc = cst[ci];
                            float zi0 = acc[mi][0 + vh][e]   + sB[u0];
                            float zi1 = acc[mi][0 + vh][e+1] + sB[u0 + 1];
                            float zf0 = acc[mi][2 + vh][e]   + sB[64 + u0];
                            float zf1 = acc[mi][2 + vh][e+1] + sB[65 + u0];
                            float zg0 = acc[mi][4 + vh][e]   + sB[128 + u0];
                            float zg1 = acc[mi][4 + vh][e+1] + sB[129 + u0];
                            float zo0 = acc[mi][6 + vh][e]   + sB[192 + u0];
                            float zo1 = acc[mi][6 + vh][e+1] + sB[193 + u0];
                            float cn0 = sigf(zf0) * cc.x + sigf(zi0) * tanhv(zg0);
                            float cn1 = sigf(zf1) * cc.y + sigf(zi1) * tanhv(zg1);
                            float hn0 = sigf(zo0) * tanhv(cn0);
                            float hn1 = sigf(zo1) * tanhv(cn1);
                            cst[ci] = make_float2(cn0, cn1);
                            *(__half2*)(hdst + swz((u32)(nn * 128 + u0 * 2))) =
                                __floats2half2_rn(hn0, hn1);
                            if (l == 1)
                                *(float2*)&hs_o[(size_t)nn * 64 + u0] = make_float2(hn0, hn1);
                        }
                    }
            }
            if (l == 1) CP_WAIT0();
            __syncthreads();
        }
    }
}

// ---------------- 1x1 conv over channels (heads*T -> T) ----------------
__global__ void conv_kernel(const float* __restrict__ conv_w,
                            const float* __restrict__ conv_b,
                            float* __restrict__ out)
{
    __shared__ float ws[TLEN * 96];
    const int tid = threadIdx.x;
    for (int i = tid; i < TLEN * 96; i += 256) ws[i] = conv_w[i];
    __syncthreads();

    const size_t P = (size_t)NNODES * HD;
    const size_t base = ((size_t)blockIdx.x * 256 + tid) * 4;

    float4 accv[TLEN];
    #pragma unroll
    for (int o = 0; o < TLEN; o++) {
        float b = conv_b[o];
        accv[o] = make_float4(b, b, b, b);
    }
    #pragma unroll 4
    for (int c = 0; c < 96; c++) {
        float4 v = *(const float4*)&g_hs[(size_t)c * P + base];
        #pragma unroll
        for (int o = 0; o < TLEN; o++) {
            float wv = ws[o * 96 + c];
            accv[o].x += wv * v.x; accv[o].y += wv * v.y;
            accv[o].z += wv * v.z; accv[o].w += wv * v.w;
        }
    }
    #pragma unroll
    for (int o = 0; o < TLEN; o++)
        *(float4*)&out[(size_t)o * P + base] = accv[o];
}

extern "C" void kernel_launch(void* const* d_in, const int* in_sizes, int n_in,
                              void* d_out, int out_size)
{
    const float* x   = (const float*)d_in[0];
    const float* Wih = (const float*)d_in[1];
    const float* Whh = (const float*)d_in[2];
    const float* bih = (const float*)d_in[3];
    const float* bhh = (const float*)d_in[4];
    const float* h0  = (const float*)d_in[5];
    const float* c0  = (const float*)d_in[6];
    const float* cw  = (const float*)d_in[7];
    const float* cb  = (const float*)d_in[8];
    float* out = (float*)d_out;

    cudaFuncSetAttribute(lstm_fused, cudaFuncAttributeMaxDynamicSharedMemorySize, SMEM_TOTAL);

    prep_w_kernel<<<2048, 256>>>(Wih, Whh);
    prep_bias_kernel<<<16, 256>>>(bih, bhh);
    prep_x_kernel<<<(TLEN * NNODES * HD + 255) / 256, 256>>>(x);
    prep_h0_kernel<<<(2 * 8 * NNODES * HD + 255) / 256, 256>>>(h0);

    dim3 grid(NNODES / 128, NHEADS);
    lstm_fused<<<grid, 512, SMEM_TOTAL>>>(c0);

    conv_kernel<<<(NNODES * HD) / 1024, 256>>>(cw, cb, out);
}

// round 8
// speedup vs baseline: 5.0899x; 1.3235x over previous
#include <cuda_runtime.h>
#include <cuda_fp16.h>
#include <cstdint>

#define NNODES 16384
#define HD 64
#define TLEN 12
#define NHEADS 8

typedef uint32_t u32;

// ---------------- device globals (allocation-free scratch) ----------------
__device__ __half g_wh[2 * 2 * 8 * 256 * 64];   // [(l*2+s)*8+a][row-perm 256][64] fp16
__device__ float  g_bias[2 * 8 * 256];          // b_ih+b_hh, natural gate order
__device__ __half g_xh[TLEN * NNODES * HD];     // x fp16
__device__ __half g_hsh[8 * TLEN * NNODES * HD];// layer-1 h fp16, ch = a*12+t

// ---------------- helpers ----------------
__device__ __forceinline__ u32 swz(u32 o) { return o ^ ((o >> 3) & 0x70); }
__device__ __forceinline__ float tanha(float x) {
    float r; asm("tanh.approx.f32 %0, %1;" : "=f"(r) : "f"(x)); return r;
}
__device__ __forceinline__ float siga(float x) {        // 1 MUFU + 1 mul + 1 fma
    return __fmaf_rn(0.5f, tanha(0.5f * x), 0.5f);
}
__device__ __forceinline__ void cpasync16(u32 saddr, const void* gaddr) {
    asm volatile("cp.async.cg.shared.global [%0], [%1], 16;" :: "r"(saddr), "l"(gaddr));
}
#define CP_COMMIT() asm volatile("cp.async.commit_group;" ::: "memory")
#define CP_WAIT(n)  asm volatile("cp.async.wait_group %0;" :: "n"(n) : "memory")

__device__ __forceinline__ void ldsm4(u32& r0, u32& r1, u32& r2, u32& r3, u32 addr) {
    asm volatile("ldmatrix.sync.aligned.m8n8.x4.shared.b16 {%0,%1,%2,%3}, [%4];"
                 : "=r"(r0), "=r"(r1), "=r"(r2), "=r"(r3) : "r"(addr));
}
__device__ __forceinline__ void barwg(int wg) {
    asm volatile("bar.sync %0, 256;" :: "r"(wg + 1) : "memory");
}

// ---------------- prep kernels ----------------
__global__ void prep_w_kernel(const float* __restrict__ Wih, const float* __restrict__ Whh) {
    int idx = blockIdx.x * 256 + threadIdx.x;        // 524288
    if (idx >= 2 * 2 * 8 * 256 * 64) return;
    int j  = idx & 63;
    int rp = (idx >> 6) & 255;
    int a  = (idx >> 14) & 7;
    int s  = (idx >> 17) & 1;
    int l  = idx >> 18;
    int u = ((rp >> 6) << 4) | (rp & 15);
    int g = (rp >> 4) & 3;
    const float* W = s ? Whh : Wih;
    float v = W[(((size_t)(l * 8 + a)) * 256 + (g * 64 + u)) * 64 + j];
    g_wh[((size_t)((l * 2 + s) * 8 + a)) * 16384 + rp * 64 + j] = __float2half_rn(v);
}

__global__ void prep_bias_kernel(const float* __restrict__ bih, const float* __restrict__ bhh) {
    int idx = blockIdx.x * 256 + threadIdx.x;
    if (idx < 2 * 8 * 256) g_bias[idx] = bih[idx] + bhh[idx];
}

__global__ void prep_x_kernel(const float* __restrict__ x) {
    int idx = blockIdx.x * 256 + threadIdx.x;
    if (idx < TLEN * NNODES * HD) g_xh[idx] = __float2half_rn(x[idx]);
}

// ---------------- fused LSTM: 2 layers x 12 steps, 2 anti-phase warpgroups ----------------
#define S_W    0u          // 4 x 32KB weight chunks (l*2+c)
#define S_BIAS 131072u     // 512 floats
#define S_WG   133120u     // per-wg 32KB: X0(8K) X1(8K) H0(8K) H1(8K)
#define SMEM_TOTAL (133120 + 2 * 32768)

__global__ void __launch_bounds__(512, 1)
lstm_fused(const float* __restrict__ h0g, const float* __restrict__ c0)
{
    extern __shared__ __align__(1024) char smem[];
    const u32 sb = (u32)__cvta_generic_to_shared(smem);

    const int tid  = threadIdx.x;
    const int lane = tid & 31;
    const int wg   = tid >> 8;           // 0/1: independent 64-node streams
    const int wtid = tid & 255;
    const int wl   = (tid >> 5) & 7;     // warp within wg
    const int wm   = wl & 1;             // M block (32 rows)
    const int wn   = wl >> 1;            // N block (64 cols)
    const int a    = blockIdx.y;
    const int tile = blockIdx.x * 128;
    const int nb   = tile + wg * 64;     // this wg's global node base

    const u32 WGB = sb + S_WG + wg * 32768;
    const u32 AX  = WGB;                 // 2 x 8KB
    const u32 AH0 = WGB + 16384;
    const u32 AH1 = WGB + 24576;
    char* WGP = smem + S_WG + wg * 32768;

    // ---- stage weights (whole CTA, 4 x 32KB) ----
    #pragma unroll
    for (int i = 0; i < 16; i++) {
        int idx = tid + i * 512;
        int ci = idx >> 11, rem = idx & 2047;
        int r = rem >> 3, j = rem & 7;
        cpasync16(sb + S_W + ci * 32768 + swz((u32)(r * 128 + j * 16)),
                  g_wh + ((size_t)(ci * 8 + a)) * 16384 + r * 64 + j * 8);
    }
    // ---- stage x(0) for this wg ----
    #pragma unroll
    for (int i = 0; i < 2; i++) {
        int idx = wtid + i * 256;
        int r = idx >> 3, j = idx & 7;
        cpasync16(AX + swz((u32)(r * 128 + j * 16)),
                  g_xh + ((size_t)nb + r) * 64 + j * 8);
    }
    CP_COMMIT();

    // ---- bias -> smem ----
    {
        float* sB = (float*)(smem + S_BIAS);
        sB[tid] = g_bias[((tid >> 8) * 8 + a) * 256 + (tid & 255)];
    }

    // ---- h0 fp32 -> fp16 smem tiles (direct loads, no prep kernel) ----
    {
        int row = wtid & 63;
        int cb  = (wtid >> 6) * 16;
        #pragma unroll
        for (int l = 0; l < 2; l++) {
            const float* src = h0g + (((size_t)(a * 2 + l)) * NNODES + nb + row) * 64 + cb;
            char* dst = WGP + (l ? 24576 : 16384);
            #pragma unroll
            for (int k = 0; k < 4; k++) {
                float4 v = *(const float4*)(src + k * 4);
                u32 off = (u32)(row * 128 + (cb + k * 4) * 2);
                *(__half2*)(dst + swz(off))     = __floats2half2_rn(v.x, v.y);
                *(__half2*)(dst + swz(off + 4)) = __floats2half2_rn(v.z, v.w);
            }
        }
    }

    // ---- c state in registers ----
    float2 cst[16];
    #pragma unroll
    for (int l = 0; l < 2; l++)
        #pragma unroll
        for (int mi = 0; mi < 2; mi++)
            #pragma unroll
            for (int rs = 0; rs < 2; rs++)
                #pragma unroll
                for (int vh = 0; vh < 2; vh++) {
                    int nn = wm * 32 + mi * 16 + (lane >> 2) + rs * 8;
                    int u0 = wn * 16 + vh * 8 + (lane & 3) * 2;
                    cst[l * 8 + mi * 4 + rs * 2 + vh] =
                        *(const float2*)&c0[(((size_t)(a * 2 + l)) * NNODES + nb + nn) * 64 + u0];
                }

    CP_WAIT(0);
    __syncthreads();

    float acc[2][8][4];

    for (int t = 0; t < TLEN; t++) {
        // prefetch next x tile for this wg
        if (t + 1 < TLEN) {
            #pragma unroll
            for (int i = 0; i < 2; i++) {
                int idx = wtid + i * 256;
                int r = idx >> 3, j = idx & 7;
                cpasync16(AX + (((t + 1) & 1) * 8192) + swz((u32)(r * 128 + j * 16)),
                          g_xh + (((size_t)(t + 1) * NNODES) + nb + r) * 64 + j * 8);
            }
            CP_COMMIT();
            CP_WAIT(1);          // waits everything except the stage just issued
        } else {
            CP_WAIT(0);
        }
        barwg(wg);

        #pragma unroll
        for (int l = 0; l < 2; l++) {
            const u32 Ab0 = l ? AH0 : (AX + (t & 1) * 8192);
            const u32 Ab1 = l ? AH1 : AH0;

            #pragma unroll
            for (int mi = 0; mi < 2; mi++)
                #pragma unroll
                for (int n8 = 0; n8 < 8; n8++)
                    #pragma unroll
                    for (int e = 0; e < 4; e++) acc[mi][n8][e] = 0.0f;

            // ---- GEMM: 2 K-chunks of 64 ----
            #pragma unroll
            for (int c = 0; c < 2; c++) {
                const u32 Ab = c ? Ab1 : Ab0;
                const u32 Wb = sb + S_W + (l * 2 + c) * 32768;
                #pragma unroll
                for (int ks = 0; ks < 4; ks++) {
                    const int kb = ks * 32;
                    u32 av[2][4];
                    #pragma unroll
                    for (int mi = 0; mi < 2; mi++) {
                        u32 off = (u32)((wm * 32 + mi * 16 + (lane & 15)) * 128 + kb + ((lane >> 4) << 4));
                        ldsm4(av[mi][0], av[mi][1], av[mi][2], av[mi][3], Ab + swz(off));
                    }
                    #pragma unroll
                    for (int i = 0; i < 4; i++) {
                        u32 off = (u32)((wn * 64 + i * 16 + (lane & 15)) * 128 + kb + ((lane >> 4) << 4));
                        u32 b0, b1, b2, b3;
                        ldsm4(b0, b1, b2, b3, Wb + swz(off));
                        #pragma unroll
                        for (int mi = 0; mi < 2; mi++) {
                            asm volatile(
                                "mma.sync.aligned.m16n8k16.row.col.f32.f16.f16.f32 "
                                "{%0,%1,%2,%3},{%4,%5,%6,%7},{%8,%9},{%0,%1,%2,%3};"
                                : "+f"(acc[mi][i*2][0]), "+f"(acc[mi][i*2][1]),
                                  "+f"(acc[mi][i*2][2]), "+f"(acc[mi][i*2][3])
                                : "r"(av[mi][0]), "r"(av[mi][1]), "r"(av[mi][2]), "r"(av[mi][3]),
                                  "r"(b0), "r"(b2));
                            asm volatile(
                                "mma.sync.aligned.m16n8k16.row.col.f32.f16.f16.f32 "
                                "{%0,%1,%2,%3},{%4,%5,%6,%7},{%8,%9},{%0,%1,%2,%3};"
                                : "+f"(acc[mi][i*2+1][0]), "+f"(acc[mi][i*2+1][1]),
                                  "+f"(acc[mi][i*2+1][2]), "+f"(acc[mi][i*2+1][3])
                                : "r"(av[mi][0]), "r"(av[mi][1]), "r"(av[mi][2]), "r"(av[mi][3]),
                                  "r"(b1), "r"(b3));
                        }
                    }
                }
            }
            barwg(wg);     // all wg warps done reading A tiles

            // ---- epilogue: single-MUFU activations, h -> smem (and hs fp16) ----
            {
                const float* sB = (const float*)(smem + S_BIAS) + l * 256;
                char* hdst = WGP + (l ? 24576 : 16384);
                __half2* hs_o = (__half2*)(g_hsh + (((size_t)(a * TLEN + t)) * NNODES + nb) * 64);
                #pragma unroll
                for (int mi = 0; mi < 2; mi++)
                    #pragma unroll
                    for (int rs = 0; rs < 2; rs++) {
                        const int nn = wm * 32 + mi * 16 + (lane >> 2) + rs * 8;
                        const int e = rs * 2;
                        #pragma unroll
                        for (int vh = 0; vh < 2; vh++) {
                            const int u0 = wn * 16 + vh * 8 + (lane & 3) * 2;
                            const int ci = l * 8 + mi * 4 + rs * 2 + vh;
                            float2 cc = cst[ci];
                            float zi0 = acc[mi][0 + vh][e]   + sB[u0];
                            float zi1 = acc[mi][0 + vh][e+1] + sB[u0 + 1];
                            float zf0 = acc[mi][2 + vh][e]   + sB[64 + u0];
                            float zf1 = acc[mi][2 + vh][e+1] + sB[65 + u0];
                            float zg0 = acc[mi][4 + vh][e]   + sB[128 + u0];
                            float zg1 = acc[mi][4 + vh][e+1] + sB[129 + u0];
                            float zo0 = acc[mi][6 + vh][e]   + sB[192 + u0];
                            float zo1 = acc[mi][6 + vh][e+1] + sB[193 + u0];
                            float cn0 = siga(zf0) * cc.x + siga(zi0) * tanha(zg0);
                            float cn1 = siga(zf1) * cc.y + siga(zi1) * tanha(zg1);
                            float hn0 = siga(zo0) * tanha(cn0);
                            float hn1 = siga(zo1) * tanha(cn1);
                            cst[ci] = make_float2(cn0, cn1);
                            __half2 hp = __floats2half2_rn(hn0, hn1);
                            *(__half2*)(hdst + swz((u32)(nn * 128 + u0 * 2))) = hp;
                            if (l == 1) hs_o[(nn * 64 + u0) >> 1] = hp;
                        }
                    }
            }
            barwg(wg);     // h writes visible before next GEMM reads
        }
    }
}

// ---------------- 1x1 conv over channels (heads*T -> T), fp16 input ----------------
__global__ void conv_kernel(const float* __restrict__ conv_w,
                            const float* __restrict__ conv_b,
                            float* __restrict__ out)
{
    __shared__ float ws[TLEN * 96];
    const int tid = threadIdx.x;
    for (int i = tid; i < TLEN * 96; i += 256) ws[i] = conv_w[i];
    __syncthreads();

    const size_t P = (size_t)NNODES * HD;
    const size_t base = ((size_t)blockIdx.x * 256 + tid) * 4;   // half units

    float4 accv[TLEN];
    #pragma unroll
    for (int o = 0; o < TLEN; o++) {
        float b = conv_b[o];
        accv[o] = make_float4(b, b, b, b);
    }
    #pragma unroll 4
    for (int c = 0; c < 96; c++) {
        uint2 raw = *(const uint2*)&g_hsh[(size_t)c * P + base];
        float2 f0 = __half22float2(*(__half2*)&raw.x);
        float2 f1 = __half22float2(*(__half2*)&raw.y);
        #pragma unroll
        for (int o = 0; o < TLEN; o++) {
            float wv = ws[o * 96 + c];
            accv[o].x += wv * f0.x; accv[o].y += wv * f0.y;
            accv[o].z += wv * f1.x; accv[o].w += wv * f1.y;
        }
    }
    #pragma unroll
    for (int o = 0; o < TLEN; o++)
        *(float4*)&out[(size_t)o * P + base] = accv[o];
}

extern "C" void kernel_launch(void* const* d_in, const int* in_sizes, int n_in,
                              void* d_out, int out_size)
{
    const float* x   = (const float*)d_in[0];
    const float* Wih = (const float*)d_in[1];
    const float* Whh = (const float*)d_in[2];
    const float* bih = (const float*)d_in[3];
    const float* bhh = (const float*)d_in[4];
    const float* h0  = (const float*)d_in[5];
    const float* c0  = (const float*)d_in[6];
    const float* cw  = (const float*)d_in[7];
    const float* cb  = (const float*)d_in[8];
    float* out = (float*)d_out;

    cudaFuncSetAttribute(lstm_fused, cudaFuncAttributeMaxDynamicSharedMemorySize, SMEM_TOTAL);

    prep_w_kernel<<<2048, 256>>>(Wih, Whh);
    prep_bias_kernel<<<16, 256>>>(bih, bhh);
    prep_x_kernel<<<(TLEN * NNODES * HD + 255) / 256, 256>>>(x);

    dim3 grid(NNODES / 128, NHEADS);
    lstm_fused<<<grid, 512, SMEM_TOTAL>>>(h0, c0);

    conv_kernel<<<(NNODES * HD) / 1024, 256>>>(cw, cb, out);
}

// round 12
// speedup vs baseline: 5.6481x; 1.1097x over previous
#include <cuda_runtime.h>
#include <cuda_fp16.h>
#include <cstdint>

#define NNODES 16384
#define HD 64
#define TLEN 12
#define NHEADS 8

typedef uint32_t u32;

// ---------------- device globals (allocation-free scratch) ----------------
__device__ __half  g_wh[2 * 2 * 8 * 256 * 64];  // [(l*2+s)*8+a][row-perm 256][64] fp16
__device__ __half2 g_bias2[2 * 8 * 3 * 32];     // 0.5*(b_ih+b_hh) half2 pairs, gates i,f,o
__device__ float   g_biasg[2 * 8 * 64];         // g-gate bias fp32
__device__ __half  g_xh[TLEN * NNODES * HD];    // x fp16
__device__ __half  g_hsh[8 * TLEN * NNODES * HD]; // layer-1 h fp16, ch = a*12+t

// ---------------- helpers ----------------
__device__ __forceinline__ u32 swz(u32 o) { return o ^ ((o >> 3) & 0x70); }
__device__ __forceinline__ float tanha(float x) {
    float r; asm("tanh.approx.f32 %0, %1;" : "=f"(r) : "f"(x)); return r;
}
__device__ __forceinline__ __half2 h2tanh_(__half2 x) {
    u32 r, xi = *(u32*)&x;
    asm("tanh.approx.f16x2 %0, %1;" : "=r"(r) : "r"(xi));
    return *(__half2*)&r;
}
__device__ __forceinline__ void cpasync16(u32 saddr, const void* gaddr) {
    asm volatile("cp.async.cg.shared.global [%0], [%1], 16;" :: "r"(saddr), "l"(gaddr));
}
#define CP_COMMIT() asm volatile("cp.async.commit_group;" ::: "memory")
#define CP_WAIT(n)  asm volatile("cp.async.wait_group %0;" :: "n"(n) : "memory")
#define PH()        asm volatile("bar.sync 1, 512;" ::: "memory")

__device__ __forceinline__ void ldsm4(u32& r0, u32& r1, u32& r2, u32& r3, u32 addr) {
    asm volatile("ldmatrix.sync.aligned.m8n8.x4.shared.b16 {%0,%1,%2,%3}, [%4];"
                 : "=r"(r0), "=r"(r1), "=r"(r2), "=r"(r3) : "r"(addr));
}

// ---------------- prep kernels ----------------
// row perm: rp = (u>>4)*64 + g*16 + (u&15)
__global__ void prep_w_kernel(const float* __restrict__ Wih, const float* __restrict__ Whh) {
    int idx = blockIdx.x * 256 + threadIdx.x;        // 524288
    if (idx >= 2 * 2 * 8 * 256 * 64) return;
    int j  = idx & 63;
    int rp = (idx >> 6) & 255;
    int a  = (idx >> 14) & 7;
    int s  = (idx >> 17) & 1;
    int l  = idx >> 18;
    int ublk = rp >> 6, rem = rp & 63;
    int g = rem >> 4, u = (ublk << 4) | (rem & 15);
    const float* W = s ? Whh : Wih;
    float v = W[(((size_t)(l * 8 + a)) * 256 + (g * 64 + u)) * 64 + j];
    g_wh[((size_t)((l * 2 + s) * 8 + a)) * 16384 + rp * 64 + j] = __float2half_rn(v);
}

__global__ void prep_bias_kernel(const float* __restrict__ bih, const float* __restrict__ bhh) {
    int idx = blockIdx.x * 256 + threadIdx.x;
    // i,f,o half2 (pre-scaled 0.5): 2*8*3*32 = 1536 entries
    if (idx < 1536) {
        int u2 = idx & 31;
        int gs = (idx >> 5) % 3;         // 0:i 1:f 2:o
        int la = idx / 96;
        const int gmap[3] = {0, 1, 3};
        int g = gmap[gs];
        int b0 = la * 256 + g * 64 + u2 * 2;
        float v0 = 0.5f * (bih[b0] + bhh[b0]);
        float v1 = 0.5f * (bih[b0 + 1] + bhh[b0 + 1]);
        g_bias2[idx] = __floats2half2_rn(v0, v1);
    }
    // g-gate fp32: 2*8*64 = 1024
    if (idx < 1024) {
        int u = idx & 63, la = idx >> 6;
        int b = la * 256 + 2 * 64 + u;
        g_biasg[idx] = bih[b] + bhh[b];
    }
}

__global__ void prep_x_kernel(const float* __restrict__ x) {
    int idx = blockIdx.x * 256 + threadIdx.x;
    if (idx < TLEN * NNODES * HD) g_xh[idx] = __float2half_rn(x[idx]);
}

// ---------------- fused LSTM: 2 layers x 12 steps, phase-alternated warpgroups ----------------
#define S_W    0u          // 4 x 32KB weight chunks (l*2+c)
#define S_BIAS 131072u     // 768B half2 bias + 512B g-bias
#define S_WG   133120u     // per-wg 32KB: X0(8K) X1(8K) H0(8K) H1(8K)
#define SMEM_TOTAL (133120 + 2 * 32768)

__global__ void __launch_bounds__(512, 1)
lstm_fused(const float* __restrict__ h0g, const float* __restrict__ c0)
{
    extern __shared__ __align__(1024) char smem[];
    const u32 sb = (u32)__cvta_generic_to_shared(smem);

    const int tid  = threadIdx.x;
    const int lane = tid & 31;
    const int wg   = tid >> 8;           // 0/1: independent 64-node streams
    const int wtid = tid & 255;
    const int wl   = (tid >> 5) & 7;
    const int wm   = wl & 1;             // M block (32 rows)
    const int wn   = wl >> 1;            // N block (64 cols)
    const int a    = blockIdx.y;
    const int tile = blockIdx.x * 128;
    const int nb   = tile + wg * 64;

    const u32 WGB = sb + S_WG + wg * 32768;
    const u32 AX  = WGB;                 // 2 x 8KB
    const u32 AH0 = WGB + 16384;
    const u32 AH1 = WGB + 24576;
    char* WGP = smem + S_WG + wg * 32768;

    // ---- stage weights (whole CTA, 4 x 32KB) ----
    #pragma unroll
    for (int i = 0; i < 16; i++) {
        int idx = tid + i * 512;
        int ci = idx >> 11, rem = idx & 2047;
        int r = rem >> 3, j = rem & 7;
        cpasync16(sb + S_W + ci * 32768 + swz((u32)(r * 128 + j * 16)),
                  g_wh + ((size_t)(ci * 8 + a)) * 16384 + r * 64 + j * 8);
    }
    // ---- stage x(0) for this wg ----
    #pragma unroll
    for (int i = 0; i < 2; i++) {
        int idx = wtid + i * 256;
        int r = idx >> 3, j = idx & 7;
        cpasync16(AX + swz((u32)(r * 128 + j * 16)),
                  g_xh + ((size_t)nb + r) * 64 + j * 8);
    }
    CP_COMMIT();

    // ---- bias -> smem (half2 i/f/o + fp32 g) ----
    if (tid < 192) {
        int l = tid / 96, r = tid % 96;
        ((__half2*)(smem + S_BIAS))[tid] = g_bias2[(l * 8 + a) * 96 + r];
    }
    if (tid >= 256 && tid < 384) {
        int k = tid - 256;
        int l = k >> 6;
        ((float*)(smem + S_BIAS + 768))[k] = g_biasg[(l * 8 + a) * 64 + (k & 63)];
    }

    // ---- h0 fp32 -> fp16 smem tiles ----
    {
        int row = wtid & 63;
        int cb  = (wtid >> 6) * 16;
        #pragma unroll
        for (int l = 0; l < 2; l++) {
            const float* src = h0g + (((size_t)(a * 2 + l)) * NNODES + nb + row) * 64 + cb;
            char* dst = WGP + (l ? 24576 : 16384);
            #pragma unroll
            for (int k = 0; k < 4; k++) {
                float4 v = *(const float4*)(src + k * 4);
                u32 off = (u32)(row * 128 + (cb + k * 4) * 2);
                *(__half2*)(dst + swz(off))     = __floats2half2_rn(v.x, v.y);
                *(__half2*)(dst + swz(off + 4)) = __floats2half2_rn(v.z, v.w);
            }
        }
    }

    // ---- c state in registers ----
    float2 cst[16];
    #pragma unroll
    for (int l = 0; l < 2; l++)
        #pragma unroll
        for (int mi = 0; mi < 2; mi++)
            #pragma unroll
            for (int rs = 0; rs < 2; rs++)
                #pragma unroll
                for (int vh = 0; vh < 2; vh++) {
                    int nn = wm * 32 + mi * 16 + (lane >> 2) + rs * 8;
                    int u0 = wn * 16 + vh * 8 + (lane & 3) * 2;
                    cst[l * 8 + mi * 4 + rs * 2 + vh] =
                        *(const float2*)&c0[(((size_t)(a * 2 + l)) * NNODES + nb + nn) * 64 + u0];
                }

    CP_WAIT(0);
    __syncthreads();

    float acc[2][8][4];
    const __half2 H05 = __floats2half2_rn(0.5f, 0.5f);

    // wg1 runs one phase behind wg0 -> GEMM of one wg overlaps epilogue of the other
    if (wg == 1) PH();

    for (int t = 0; t < TLEN; t++) {
        // prefetch next x tile for this wg (runs in previous slot)
        if (t + 1 < TLEN) {
            #pragma unroll
            for (int i = 0; i < 2; i++) {
                int idx = wtid + i * 256;
                int r = idx >> 3, j = idx & 7;
                cpasync16(AX + (((t + 1) & 1) * 8192) + swz((u32)(r * 128 + j * 16)),
                          g_xh + (((size_t)(t + 1) * NNODES) + nb + r) * 64 + j * 8);
            }
            CP_COMMIT();
            CP_WAIT(1);
        } else {
            CP_WAIT(0);
        }

        #pragma unroll
        for (int l = 0; l < 2; l++) {
            const u32 Ab0 = l ? AH0 : (AX + (t & 1) * 8192);
            const u32 Ab1 = l ? AH1 : AH0;

            PH();   // ---- GEMM slot ----

            #pragma unroll
            for (int mi = 0; mi < 2; mi++)
                #pragma unroll
                for (int n8 = 0; n8 < 8; n8++)
                    #pragma unroll
                    for (int e = 0; e < 4; e++) acc[mi][n8][e] = 0.0f;

            #pragma unroll
            for (int c = 0; c < 2; c++) {
                const u32 Ab = c ? Ab1 : Ab0;
                const u32 Wb = sb + S_W + (l * 2 + c) * 32768;
                #pragma unroll
                for (int ks = 0; ks < 4; ks++) {
                    const int kb = ks * 32;
                    u32 av[2][4];
                    #pragma unroll
                    for (int mi = 0; mi < 2; mi++) {
                        u32 off = (u32)((wm * 32 + mi * 16 + (lane & 15)) * 128 + kb + ((lane >> 4) << 4));
                        ldsm4(av[mi][0], av[mi][1], av[mi][2], av[mi][3], Ab + swz(off));
                    }
                    #pragma unroll
                    for (int i = 0; i < 4; i++) {
                        u32 off = (u32)((wn * 64 + i * 16 + (lane & 15)) * 128 + kb + ((lane >> 4) << 4));
                        u32 b0, b1, b2, b3;
                        ldsm4(b0, b1, b2, b3, Wb + swz(off));
                        #pragma unroll
                        for (int mi = 0; mi < 2; mi++) {
                            asm volatile(
                                "mma.sync.aligned.m16n8k16.row.col.f32.f16.f16.f32 "
                                "{%0,%1,%2,%3},{%4,%5,%6,%7},{%8,%9},{%0,%1,%2,%3};"
                                : "+f"(acc[mi][i*2][0]), "+f"(acc[mi][i*2][1]),
                                  "+f"(acc[mi][i*2][2]), "+f"(acc[mi][i*2][3])
                                : "r"(av[mi][0]), "r"(av[mi][1]), "r"(av[mi][2]), "r"(av[mi][3]),
                                  "r"(b0), "r"(b2));
                            asm volatile(
                                "mma.sync.aligned.m16n8k16.row.col.f32.f16.f16.f32 "
                                "{%0,%1,%2,%3},{%4,%5,%6,%7},{%8,%9},{%0,%1,%2,%3};"
                                : "+f"(acc[mi][i*2+1][0]), "+f"(acc[mi][i*2+1][1]),
                                  "+f"(acc[mi][i*2+1][2]), "+f"(acc[mi][i*2+1][3])
                                : "r"(av[mi][0]), "r"(av[mi][1]), "r"(av[mi][2]), "r"(av[mi][3]),
                                  "r"(b1), "r"(b3));
                        }
                    }
                }
            }

            PH();   // ---- epilogue slot ----
            {
                const __half2* sB2 = (const __half2*)(smem + S_BIAS) + l * 96;
                const float*   sBg = (const float*)(smem + S_BIAS + 768) + l * 64;
                char* hdst = WGP + (l ? 24576 : 16384);
                __half2* hs_o = (__half2*)(g_hsh + (((size_t)(a * TLEN + t)) * NNODES + nb) * 64);
                #pragma unroll
                for (int mi = 0; mi < 2; mi++)
                    #pragma unroll
                    for (int rs = 0; rs < 2; rs++) {
                        const int nn = wm * 32 + mi * 16 + (lane >> 2) + rs * 8;
                        const int e = rs * 2;
                        #pragma unroll
                        for (int vh = 0; vh < 2; vh++) {
                            const int u0 = wn * 16 + vh * 8 + (lane & 3) * 2;
                            const int bidx = u0 >> 1;
                            const int ci = l * 8 + mi * 4 + rs * 2 + vh;
                            float2 cc = cst[ci];
                            // sigma gates in f16x2 (bias+0.5 scale folded into one HFMA2)
                            __half2 zi2 = __floats2half2_rn(acc[mi][0 + vh][e], acc[mi][0 + vh][e + 1]);
                            __half2 zf2 = __floats2half2_rn(acc[mi][2 + vh][e], acc[mi][2 + vh][e + 1]);
                            __half2 zo2 = __floats2half2_rn(acc[mi][6 + vh][e], acc[mi][6 + vh][e + 1]);
                            __half2 si2 = __hfma2(h2tanh_(__hfma2(zi2, H05, sB2[bidx])),      H05, H05);
                            __half2 sf2 = __hfma2(h2tanh_(__hfma2(zf2, H05, sB2[32 + bidx])), H05, H05);
                            __half2 so2 = __hfma2(h2tanh_(__hfma2(zo2, H05, sB2[64 + bidx])), H05, H05);
                            float2 si = __half22float2(si2);
                            float2 sf = __half22float2(sf2);
                            float2 so = __half22float2(so2);
                            // value paths fp32
                            float2 bg = *(const float2*)&sBg[u0];
                            float tg0 = tanha(acc[mi][4 + vh][e]     + bg.x);
                            float tg1 = tanha(acc[mi][4 + vh][e + 1] + bg.y);
                            float cn0 = __fmaf_rn(sf.x, cc.x, si.x * tg0);
                            float cn1 = __fmaf_rn(sf.y, cc.y, si.y * tg1);
                            float hn0 = so.x * tanha(cn0);
                            float hn1 = so.y * tanha(cn1);
                            cst[ci] = make_float2(cn0, cn1);
                            __half2 hp = __floats2half2_rn(hn0, hn1);
                            *(__half2*)(hdst + swz((u32)(nn * 128 + u0 * 2))) = hp;
                            if (l == 1) hs_o[(nn * 64 + u0) >> 1] = hp;
                        }
                    }
            }
        }
    }
    if (wg == 0) PH();   // balance wg1's leading phase
}

// ---------------- 1x1 conv over channels (heads*T -> T), fp16 input ----------------
__global__ void conv_kernel(const float* __restrict__ conv_w,
                            const float* __restrict__ conv_b,
                            float* __restrict__ out)
{
    __shared__ float ws[TLEN * 96];
    const int tid = threadIdx.x;
    for (int i = tid; i < TLEN * 96; i += 256) ws[i] = conv_w[i];
    __syncthreads();

    const size_t P = (size_t)NNODES * HD;
    const size_t base = ((size_t)blockIdx.x * 256 + tid) * 4;

    float4 accv[TLEN];
    #pragma unroll
    for (int o = 0; o < TLEN; o++) {
        float b = conv_b[o];
        accv[o] = make_float4(b, b, b, b);
    }
    #pragma unroll 4
    for (int c = 0; c < 96; c++) {
        uint2 raw = *(const uint2*)&g_hsh[(size_t)c * P + base];
        float2 f0 = __half22float2(*(__half2*)&raw.x);
        float2 f1 = __half22float2(*(__half2*)&raw.y);
        #pragma unroll
        for (int o = 0; o < TLEN; o++) {
            float wv = ws[o * 96 + c];
            accv[o].x += wv * f0.x; accv[o].y += wv * f0.y;
            accv[o].z += wv * f1.x; accv[o].w += wv * f1.y;
        }
    }
    #pragma unroll
    for (int o = 0; o < TLEN; o++)
        *(float4*)&out[(size_t)o * P + base] = accv[o];
}

extern "C" void kernel_launch(void* const* d_in, const int* in_sizes, int n_in,
                              void* d_out, int out_size)
{
    const float* x   = (const float*)d_in[0];
    const float* Wih = (const float*)d_in[1];
    const float* Whh = (const float*)d_in[2];
    const float* bih = (const float*)d_in[3];
    const float* bhh = (const float*)d_in[4];
    const float* h0  = (const float*)d_in[5];
    const float* c0  = (const float*)d_in[6];
    const float* cw  = (const float*)d_in[7];
    const float* cb  = (const float*)d_in[8];
    float* out = (float*)d_out;

    cudaFuncSetAttribute(lstm_fused, cudaFuncAttributeMaxDynamicSharedMemorySize, SMEM_TOTAL);

    prep_w_kernel<<<2048, 256>>>(Wih, Whh);
    prep_bias_kernel<<<8, 256>>>(bih, bhh);
    prep_x_kernel<<<(TLEN * NNODES * HD + 255) / 256, 256>>>(x);

    dim3 grid(NNODES / 128, NHEADS);
    lstm_fused<<<grid, 512, SMEM_TOTAL>>>(h0, c0);

    conv_kernel<<<(NNODES * HD) / 1024, 256>>>(cw, cb, out);
}